// round 7
// baseline (speedup 1.0000x reference)
#include <cuda_runtime.h>
#include <cuda_bf16.h>
#include <mma.h>
#include <cstdint>

using namespace nvcuda;

#define N_ITEMS 500000
#define DIM 64
#define BATCH 1024
#define QB 256              // queries per CTA
#define THREADS 512         // 16 warps x 16 queries each
#define ITEM_TILE 64
#define CHUNK 4096          // items per CTA chunk -> 64 tiles
#define NCHUNKS ((N_ITEMS + CHUNK - 1) / CHUNK)   // 123
#define MARGIN 1.5f         // >> 2*eps(bf16 dot) ~ 0.6 worst-case
#define NINF __uint_as_float(0xFF800000u)

// smem layout (dynamic): Q bf16 | item tile bf16 | per-warp C buf | selfs
#define SM_Q     0
#define SM_ITEM  (QB * DIM * 2)                       // 32768
#define SM_CBUF  (SM_ITEM + ITEM_TILE * DIM * 2)      // +8192 = 40960
#define SM_SELF  (SM_CBUF + 16 * 256 * 4)             // +16384 = 57344
#define SM_TOTAL (SM_SELF + QB * 4)                   // +1024 = 58368

// Cross-CTA reduction scratch: packed (ordered_float(score) << 32) | ~index
__device__ unsigned long long g_best[BATCH];

__device__ __forceinline__ unsigned int f2ord(float f) {
    unsigned int b = __float_as_uint(f);
    return (b & 0x80000000u) ? ~b : (b | 0x80000000u);
}
__device__ __forceinline__ float ord2f(unsigned int o) {
    unsigned int b = (o & 0x80000000u) ? (o & 0x7FFFFFFFu) : ~o;
    return __uint_as_float(b);
}

__global__ void reset_kernel() {
    int i = blockIdx.x * blockDim.x + threadIdx.x;
    if (i < BATCH)
        g_best[i] = ((unsigned long long)f2ord(NINF) << 32) | 0xFFFFFFFFull;
}

__global__ __launch_bounds__(THREADS, 1)
void sim_kernel(const float* __restrict__ emb,
                const int* __restrict__ item_idx) {
    extern __shared__ char smem[];
    __nv_bfloat16*  qs   = (__nv_bfloat16*)(smem + SM_Q);
    __nv_bfloat16*  its  = (__nv_bfloat16*)(smem + SM_ITEM);
    float*          cbuf = (float*)(smem + SM_CBUF);
    int*            selfs = (int*)(smem + SM_SELF);

    const int tid  = threadIdx.x;
    const int warp = tid >> 5;
    const int lane = tid & 31;
    const int qbase = blockIdx.y * QB;

    // ---- stage self indices (item_idx is int32 under JAX default promotion)
    for (int q = tid; q < QB; q += THREADS) {
        int s = item_idx[qbase + q] - 1;
        if (s < 0) s += N_ITEMS;               // python negative-index wrap
        selfs[q] = max(0, min(s, N_ITEMS - 1));
    }
    __syncthreads();

    // ---- stage query rows as bf16 (QB*16 float4 gathers, 128B/row coalesced)
    for (int i = tid; i < QB * (DIM / 4); i += THREADS) {
        int q = i >> 4, p = i & 15;
        float4 v = __ldg((const float4*)(emb + (size_t)selfs[q] * DIM) + p);
        __nv_bfloat162* dst = (__nv_bfloat162*)qs;
        dst[i * 2]     = __floats2bfloat162_rn(v.x, v.y);
        dst[i * 2 + 1] = __floats2bfloat162_rn(v.z, v.w);
    }
    __syncthreads();

    // ---- A fragments: warp's 16 query rows, all of K=64, resident for kernel
    wmma::fragment<wmma::matrix_a, 16, 16, 16, __nv_bfloat16, wmma::row_major> afrag[4];
    const int wq = warp * 16;
    #pragma unroll
    for (int kt = 0; kt < 4; kt++)
        wmma::load_matrix_sync(afrag[kt], qs + wq * DIM + kt * 16, DIM);

    // per-lane row ownership: row r = lane>>1, column half ch = lane&1
    const int r  = lane >> 1;
    const int ch = lane & 1;
    const int selfj = selfs[wq + r];
    float* cw = cbuf + warp * 256;

    float runmax = NINF;      // running APPROX max for row r (chunk-local)
    float bexact = NINF;      // exact best from rescored candidates
    int   bidx   = 0;

    const int cstart = blockIdx.x * CHUNK;
    const int cend   = min(cstart + CHUNK, N_ITEMS);

    for (int tb = cstart; tb < cend; tb += ITEM_TILE) {
        __syncthreads();  // item smem reusable

        // convert 64x64 item tile fp32 -> bf16 (coalesced, zero-pad OOB)
        for (int i = tid; i < ITEM_TILE * (DIM / 4); i += THREADS) {
            int it = i >> 4, p = i & 15;
            int j = tb + it;
            float4 v = (j < N_ITEMS)
                     ? __ldg((const float4*)(emb + (size_t)j * DIM) + p)
                     : make_float4(0.f, 0.f, 0.f, 0.f);
            __nv_bfloat162* dst = (__nv_bfloat162*)its;
            dst[i * 2]     = __floats2bfloat162_rn(v.x, v.y);
            dst[i * 2 + 1] = __floats2bfloat162_rn(v.z, v.w);
        }
        __syncthreads();

        #pragma unroll
        for (int nt = 0; nt < 4; nt++) {
            wmma::fragment<wmma::matrix_b, 16, 16, 16, __nv_bfloat16, wmma::col_major> bfrag;
            wmma::fragment<wmma::accumulator, 16, 16, 16, float> cf;
            wmma::fill_fragment(cf, 0.0f);
            #pragma unroll
            for (int kt = 0; kt < 4; kt++) {
                wmma::load_matrix_sync(bfrag, its + (nt * 16) * DIM + kt * 16, DIM);
                wmma::mma_sync(cf, afrag[kt], bfrag, cf);
            }
            wmma::store_matrix_sync(cw, cf, 16, wmma::mem_row_major);
            __syncwarp();

            // scan: lane owns row r, cols [ch*8, ch*8+8)
            const int jbase = tb + nt * 16 + ch * 8;
            float sc[8];
            float tmax = NINF;
            #pragma unroll
            for (int c = 0; c < 8; c++) {
                float s = cw[r * 16 + ch * 8 + c];
                sc[c] = s;
                int j = jbase + c;
                if (j != selfj && j < N_ITEMS) tmax = fmaxf(tmax, s);
            }
            tmax   = fmaxf(tmax, __shfl_xor_sync(0xFFFFFFFFu, tmax, 1));
            runmax = fmaxf(runmax, tmax);
            const float thr = runmax - MARGIN;

            #pragma unroll
            for (int c = 0; c < 8; c++) {
                int j = jbase + c;
                if (sc[c] >= thr && j != selfj && j < N_ITEMS) {
                    // exact fp32 rescore (rare: ~10 per row per chunk)
                    const float4* qa = (const float4*)(emb + (size_t)selfj * DIM);
                    const float4* ja = (const float4*)(emb + (size_t)j * DIM);
                    float a0 = 0.f, a1 = 0.f;
                    #pragma unroll
                    for (int p = 0; p < 16; p += 2) {
                        float4 x0 = __ldg(qa + p),     y0 = __ldg(ja + p);
                        float4 x1 = __ldg(qa + p + 1), y1 = __ldg(ja + p + 1);
                        a0 = fmaf(x0.x, y0.x, a0); a0 = fmaf(x0.y, y0.y, a0);
                        a0 = fmaf(x0.z, y0.z, a0); a0 = fmaf(x0.w, y0.w, a0);
                        a1 = fmaf(x1.x, y1.x, a1); a1 = fmaf(x1.y, y1.y, a1);
                        a1 = fmaf(x1.z, y1.z, a1); a1 = fmaf(x1.w, y1.w, a1);
                    }
                    float acc = a0 + a1;   // same order as R6 exact kernel
                    if (acc > bexact || (acc == bexact && j < bidx)) {
                        bexact = acc; bidx = j;
                    }
                }
            }
            __syncwarp();  // cw reused next nt
        }
    }

    // combine the two lanes of each row, one atomic per (row, chunk)
    float os = __shfl_xor_sync(0xFFFFFFFFu, bexact, 1);
    int   oi = __shfl_xor_sync(0xFFFFFFFFu, bidx, 1);
    if (os > bexact || (os == bexact && oi < bidx)) { bexact = os; bidx = oi; }
    if (ch == 0 && bexact > NINF) {
        unsigned long long packed =
            ((unsigned long long)f2ord(bexact) << 32) | (unsigned int)(~bidx);
        atomicMax(&g_best[qbase + wq + r], packed);
    }
}

__global__ void finalize_kernel(const float* __restrict__ minv,
                                const float* __restrict__ maxv,
                                float* __restrict__ out) {
    int i = blockIdx.x * blockDim.x + threadIdx.x;
    if (i < BATCH) {
        unsigned long long p = g_best[i];
        float raw = ord2f((unsigned int)(p >> 32));
        int   idx = (int)(~(unsigned int)(p & 0xFFFFFFFFull));
        float mn = minv[0], mx = maxv[0];
        float score = (raw - mn) / (mx - mn);
        out[i]         = (float)(idx + 1);   // indices (argmax + 1), exact < 2^24
        out[BATCH + i] = score;              // normalized scores (fp32 output)
    }
}

extern "C" void kernel_launch(void* const* d_in, const int* in_sizes, int n_in,
                              void* d_out, int out_size) {
    const float* emb = (const float*)d_in[0];
    const int*   idx = (const int*)d_in[1];
    const float* mn  = (const float*)d_in[2];
    const float* mx  = (const float*)d_in[3];

    static bool attr_set = false;
    if (!attr_set) {
        cudaFuncSetAttribute(sim_kernel,
                             cudaFuncAttributeMaxDynamicSharedMemorySize, SM_TOTAL);
        attr_set = true;
    }

    reset_kernel<<<(BATCH + 255) / 256, 256>>>();

    dim3 grid(NCHUNKS, BATCH / QB);
    sim_kernel<<<grid, THREADS, SM_TOTAL>>>(emb, idx);

    finalize_kernel<<<(BATCH + 255) / 256, 256>>>(mn, mx, (float*)d_out);
}